// round 3
// baseline (speedup 1.0000x reference)
#include <cuda_runtime.h>

#define NNODE  128
#define NEDGE  1024
#define ETOT   1152
#define HFEAT  128
#define PITCH  132          // float4-aligned padded pitch
#define NGRAPH 1024
#define NTHREADS 512
#define WCHUNK 16           // W staging chunk: 16 k-rows = 8KB

// ---------------------------------------------------------------------------
// Device-global CSR (edge template shared by all graphs).
// ---------------------------------------------------------------------------
__device__ int g_csr_ptr[NNODE + 1];
__device__ int g_csr_src[ETOT];

__global__ void build_csr_kernel(const int* __restrict__ ei) {
    __shared__ int s_src[NEDGE];
    __shared__ int s_dst[NEDGE];
    __shared__ int cnt[NNODE];
    __shared__ int base[NNODE + 1];
    int t = threadIdx.x;
    if (t < NEDGE) { s_src[t] = ei[t]; s_dst[t] = ei[NEDGE + t]; }
    if (t < NNODE) cnt[t] = 0;
    __syncthreads();
    if (t < NEDGE) atomicAdd(&cnt[s_dst[t]], 1);
    __syncthreads();
    if (t == 0) {
        int acc = 0;
        for (int d = 0; d < NNODE; ++d) { base[d] = acc; acc += cnt[d] + 1; }
        base[NNODE] = acc;
    }
    __syncthreads();
    if (t <= NNODE) g_csr_ptr[t] = base[t];
    if (t < NEDGE) {
        // stable rank within dst bucket (deterministic)
        int d = s_dst[t];
        int rank = 0;
        for (int e = 0; e < t; ++e) rank += (s_dst[e] == d) ? 1 : 0;
        g_csr_src[base[d] + rank] = s_src[t];
    }
    if (t < NNODE) g_csr_src[base[t] + cnt[t]] = t;  // self loop last
}

// ---------------------------------------------------------------------------
// Shared memory layout
// ---------------------------------------------------------------------------
constexpr int OFF_SH    = 0;
constexpr int OFF_SXH   = OFF_SH  + NNODE * PITCH;
constexpr int OFF_SW    = OFF_SXH + NNODE * PITCH;       // 2 * 16 * 128
constexpr int OFF_SEX   = OFF_SW  + 2 * WCHUNK * HFEAT;
constexpr int OFF_SS    = OFF_SEX + ETOT * 4;
constexpr int OFF_SD    = OFF_SS  + 512;
constexpr int OFF_RINV  = OFF_SD  + 512;
constexpr int OFF_SATT  = OFF_RINV + 512;
constexpr int OFF_SCALE = OFF_SATT + 256;
constexpr int OFF_BIAS  = OFF_SCALE + 128;
constexpr int OFF_POOL  = OFF_BIAS + 128;
constexpr int OFF_HP    = OFF_POOL + 512;
constexpr int OFF_ZZ    = OFF_HP + 128;
constexpr int SM_FLOATS = OFF_ZZ + 64;
constexpr int SM_INTS   = 132 + ETOT;
constexpr int SMEM_BYTES = SM_FLOATS * 4 + SM_INTS * 4;

// ---------------------------------------------------------------------------
// Packed fp32x2 helpers (FFMA2 is PTX-only; ptxas never auto-fuses)
// ---------------------------------------------------------------------------
__device__ __forceinline__ unsigned long long pack2(float a) {
    unsigned long long r;
    unsigned int ai = __float_as_uint(a);
    asm("mov.b64 %0, {%1, %1};" : "=l"(r) : "r"(ai));
    return r;
}
__device__ __forceinline__ void ffma2(unsigned long long& d,
                                      unsigned long long a,
                                      unsigned long long b) {
    asm("fma.rn.f32x2 %0, %1, %2, %0;" : "+l"(d) : "l"(a), "l"(b));
}

// ---------------------------------------------------------------------------
// C[128,128] = A(smem, PITCH) @ W(global, staged via smem double buffer).
// 512 threads. Warp tile 16 rows x 64 cols; thread tile 4 rows x 8 cols.
// Accumulators are packed f32x2 (4 x 4 pairs).
// NOTE: contains internal __syncthreads(); all threads must call it.
// The first internal sync also orders prior writes to A.
// ---------------------------------------------------------------------------
__device__ __forceinline__ void gemm128_ws(const float* __restrict__ A,
                                           const float* __restrict__ Wg,
                                           float* __restrict__ C,
                                           float* __restrict__ sW, int tid) {
    const int lane = tid & 31;
    const int wid  = tid >> 5;
    const int wr = wid >> 1, wc = wid & 1;
    const int r0 = wr * 16 + (lane >> 3) * 4;
    const int c0 = wc * 64 + (lane & 7) * 8;

    unsigned long long acc[4][4];
#pragma unroll
    for (int i = 0; i < 4; ++i)
#pragma unroll
        for (int j = 0; j < 4; ++j) acc[i][j] = 0ull;

    // staging slice: thread loads one float4 per chunk
    const int srow = tid >> 5;          // 0..15
    const int scol = (tid & 31) * 4;    // 0..124

    float4 pre = *(const float4*)(Wg + srow * HFEAT + scol);
    *(float4*)(sW + srow * HFEAT + scol) = pre;
    __syncthreads();

    constexpr int NCH = HFEAT / WCHUNK;   // 8
    for (int ch = 0; ch < NCH; ++ch) {
        if (ch + 1 < NCH)
            pre = *(const float4*)(Wg + ((ch + 1) * WCHUNK + srow) * HFEAT + scol);
        const float* wb = sW + (ch & 1) * (WCHUNK * HFEAT);
        const int kbase = ch * WCHUNK;
#pragma unroll
        for (int kq = 0; kq < WCHUNK / 4; ++kq) {
            float4 a[4];
#pragma unroll
            for (int i = 0; i < 4; ++i)
                a[i] = *(const float4*)(A + (r0 + i) * PITCH + kbase + kq * 4);
#pragma unroll
            for (int kk = 0; kk < 4; ++kk) {
                ulonglong2 w0 = *(const ulonglong2*)(wb + (kq * 4 + kk) * HFEAT + c0);
                ulonglong2 w1 = *(const ulonglong2*)(wb + (kq * 4 + kk) * HFEAT + c0 + 4);
#pragma unroll
                for (int i = 0; i < 4; ++i) {
                    float av = (kk == 0) ? a[i].x : (kk == 1) ? a[i].y
                             : (kk == 2) ? a[i].z : a[i].w;
                    unsigned long long ap = pack2(av);
                    ffma2(acc[i][0], ap, w0.x);
                    ffma2(acc[i][1], ap, w0.y);
                    ffma2(acc[i][2], ap, w1.x);
                    ffma2(acc[i][3], ap, w1.y);
                }
            }
        }
        __syncthreads();
        if (ch + 1 < NCH) {
            float* wb2 = sW + ((ch + 1) & 1) * (WCHUNK * HFEAT);
            *(float4*)(wb2 + srow * HFEAT + scol) = pre;
            __syncthreads();
        }
    }

#pragma unroll
    for (int i = 0; i < 4; ++i) {
        ulonglong2 s0, s1;
        s0.x = acc[i][0]; s0.y = acc[i][1];
        s1.x = acc[i][2]; s1.y = acc[i][3];
        *(ulonglong2*)(C + (r0 + i) * PITCH + c0)     = s0;
        *(ulonglong2*)(C + (r0 + i) * PITCH + c0 + 4) = s1;
    }
}

__global__ __launch_bounds__(NTHREADS, 1)
void gnn_kernel(const float* __restrict__ x,
                const float* __restrict__ w_in, const float* __restrict__ b_in,
                const float* __restrict__ g0w, const float* __restrict__ g0as,
                const float* __restrict__ g0ad, const float* __restrict__ g0b,
                const float* __restrict__ bn0g, const float* __restrict__ bn0b,
                const float* __restrict__ bn0m, const float* __restrict__ bn0v,
                const float* __restrict__ g1w, const float* __restrict__ g1as,
                const float* __restrict__ g1ad, const float* __restrict__ g1b,
                const float* __restrict__ bn1g, const float* __restrict__ bn1b,
                const float* __restrict__ bn1m, const float* __restrict__ bn1v,
                const float* __restrict__ w1, const float* __restrict__ b1,
                const float* __restrict__ w2, const float* __restrict__ b2,
                float* __restrict__ out) {
    extern __shared__ float smem[];
    float* sh    = smem + OFF_SH;
    float* sxh   = smem + OFF_SXH;
    float* sW    = smem + OFF_SW;
    float* sex   = smem + OFF_SEX;
    float* s_s   = smem + OFF_SS;
    float* s_d   = smem + OFF_SD;
    float* rinv  = smem + OFF_RINV;
    float* satt  = smem + OFF_SATT;
    float* sscale= smem + OFF_SCALE;
    float* sbias = smem + OFF_BIAS;
    float* pool  = smem + OFF_POOL;
    float* hp    = smem + OFF_HP;
    float* zz    = smem + OFF_ZZ;
    int*   sptr  = (int*)(smem + SM_FLOATS);
    int*   scsr  = sptr + 132;

    const int tid  = threadIdx.x;
    const int wid  = tid >> 5;
    const int lane = tid & 31;
    const int b    = blockIdx.x;

    // stage CSR
    for (int i = tid; i <= NNODE; i += NTHREADS) sptr[i] = g_csr_ptr[i];
    for (int i = tid; i < ETOT; i += NTHREADS)   scsr[i] = g_csr_src[i];

    // stage layer-0 attention + fold BN0:  out = agg*rinv*scale + bias_tot
    if (tid < 128) {
        satt[tid]       = g0as[tid];
        satt[128 + tid] = g0ad[tid];
        float sc = bn0g[tid] * rsqrtf(bn0v[tid] + 1e-5f);
        sscale[tid] = sc;
        sbias[tid]  = fmaf(g0b[tid] - bn0m[tid], sc, bn0b[tid]);
    }

    // -------- input projection --------
    const float* xr = x + b * NNODE;
    for (int it = tid; it < NNODE * 32; it += NTHREADS) {
        int n = it >> 5, fq = it & 31;
        float xv = xr[n];
        float4 w  = *(const float4*)(w_in + fq * 4);
        float4 bb = *(const float4*)(b_in + fq * 4);
        float4 r;
        r.x = fmaxf(fmaf(xv, w.x, bb.x), 0.0f);
        r.y = fmaxf(fmaf(xv, w.y, bb.y), 0.0f);
        r.z = fmaxf(fmaf(xv, w.z, bb.z), 0.0f);
        r.w = fmaxf(fmaf(xv, w.w, bb.w), 0.0f);
        *(float4*)(sh + n * PITCH + fq * 4) = r;
    }
    // gemm's first internal __syncthreads orders sh writes before A reads
    gemm128_ws(sh, g0w, sxh, sW, tid);
    __syncthreads();

    // per-(node, head) scores
    {
        int n  = tid & 127;
        int hh = tid >> 7;
        const float* row = &sxh[n * PITCH + hh * 32];
        const float* as  = &satt[hh * 32];
        const float* ad  = &satt[128 + hh * 32];
        float ssum = 0.0f, dsum = 0.0f;
#pragma unroll
        for (int q = 0; q < 8; ++q) {
            float4 v  = *(const float4*)(row + q * 4);
            float4 a1 = *(const float4*)(as + q * 4);
            float4 a2 = *(const float4*)(ad + q * 4);
            ssum = fmaf(v.x, a1.x, fmaf(v.y, a1.y, fmaf(v.z, a1.z, fmaf(v.w, a1.w, ssum))));
            dsum = fmaf(v.x, a2.x, fmaf(v.y, a2.y, fmaf(v.z, a2.z, fmaf(v.w, a2.w, dsum))));
        }
        s_s[n * 4 + hh] = ssum;
        s_d[n * 4 + hh] = dsum;
    }
    __syncthreads();

    // softmax per (dst, head)
    {
        int d  = tid & 127;
        int hh = tid >> 7;
        int beg = sptr[d], end = sptr[d + 1];
        float sd = s_d[d * 4 + hh];
        float mx = -1e30f;
        for (int p = beg; p < end; ++p) {
            float e = s_s[scsr[p] * 4 + hh] + sd;
            e = (e > 0.0f) ? e : 0.2f * e;
            mx = fmaxf(mx, e);
        }
        float sum = 0.0f;
        for (int p = beg; p < end; ++p) {
            float e = s_s[scsr[p] * 4 + hh] + sd;
            e = (e > 0.0f) ? e : 0.2f * e;
            float ex = __expf(e - mx);
            sex[p * 4 + hh] = ex;
            sum += ex;
        }
        rinv[d * 4 + hh] = 1.0f / sum;
    }
    __syncthreads();

    // aggregate + BN0 + relu (warp-per-node, float4 per lane) -> sh
    {
        int hh = lane >> 3;
        float4 sc = *(const float4*)(sscale + lane * 4);
        float4 bs = *(const float4*)(sbias + lane * 4);
        for (int d = wid; d < NNODE; d += 16) {
            int beg = sptr[d], end = sptr[d + 1];
            float rv = rinv[d * 4 + hh];
            float4 acc = make_float4(0.f, 0.f, 0.f, 0.f);
            for (int p = beg; p < end; ++p) {
                float w = sex[p * 4 + hh];
                const float4 v = *(const float4*)(sxh + scsr[p] * PITCH + lane * 4);
                acc.x = fmaf(w, v.x, acc.x);
                acc.y = fmaf(w, v.y, acc.y);
                acc.z = fmaf(w, v.z, acc.z);
                acc.w = fmaf(w, v.w, acc.w);
            }
            float4 r;
            r.x = fmaxf(fmaf(acc.x * rv, sc.x, bs.x), 0.0f);
            r.y = fmaxf(fmaf(acc.y * rv, sc.y, bs.y), 0.0f);
            r.z = fmaxf(fmaf(acc.z * rv, sc.z, bs.z), 0.0f);
            r.w = fmaxf(fmaf(acc.w * rv, sc.w, bs.w), 0.0f);
            *(float4*)(sh + d * PITCH + lane * 4) = r;
        }
    }
    __syncthreads();   // all layer-0 reads of sscale/sbias/satt done

    // stage layer-1 attention + BN1 fold (race-free: after sync above,
    // first reads happen after gemm's internal syncs)
    if (tid < 128) {
        float sc = bn1g[tid] * rsqrtf(bn1v[tid] + 1e-5f);
        sscale[tid] = sc;
        sbias[tid]  = fmaf(g1b[tid] - bn1m[tid], sc, bn1b[tid]);
        satt[tid]       = g1as[tid];
        satt[128 + tid] = g1ad[tid];
    }

    // ==================== GAT layer 1 ====================
    gemm128_ws(sh, g1w, sxh, sW, tid);
    __syncthreads();

    // scores: warp per node, shuffle reduce
    {
        float4 a1 = *(const float4*)(satt + lane * 4);
        float4 a2 = *(const float4*)(satt + 128 + lane * 4);
        for (int nd = wid; nd < NNODE; nd += 16) {
            float4 v = *(const float4*)(sxh + nd * PITCH + lane * 4);
            float ss = v.x*a1.x + v.y*a1.y + v.z*a1.z + v.w*a1.w;
            float dd = v.x*a2.x + v.y*a2.y + v.z*a2.z + v.w*a2.w;
#pragma unroll
            for (int o = 16; o; o >>= 1) {
                ss += __shfl_xor_sync(0xffffffffu, ss, o);
                dd += __shfl_xor_sync(0xffffffffu, dd, o);
            }
            if (lane == 0) { s_s[nd] = ss; s_d[nd] = dd; }
        }
    }
    __syncthreads();

    if (tid < 128) {
        int d = tid;
        int beg = sptr[d], end = sptr[d + 1];
        float sd = s_d[d];
        float mx = -1e30f;
        for (int p = beg; p < end; ++p) {
            float e = s_s[scsr[p]] + sd;
            e = (e > 0.0f) ? e : 0.2f * e;
            mx = fmaxf(mx, e);
        }
        float sum = 0.0f;
        for (int p = beg; p < end; ++p) {
            float e = s_s[scsr[p]] + sd;
            e = (e > 0.0f) ? e : 0.2f * e;
            float ex = __expf(e - mx);
            sex[p] = ex;
            sum += ex;
        }
        rinv[d] = 1.0f / sum;
    }
    __syncthreads();

    // aggregate + BN1 + relu -> sh
    {
        float4 sc = *(const float4*)(sscale + lane * 4);
        float4 bs = *(const float4*)(sbias + lane * 4);
        for (int d = wid; d < NNODE; d += 16) {
            int beg = sptr[d], end = sptr[d + 1];
            float rv = rinv[d];
            float4 acc = make_float4(0.f, 0.f, 0.f, 0.f);
            for (int p = beg; p < end; ++p) {
                float w = sex[p];
                const float4 v = *(const float4*)(sxh + scsr[p] * PITCH + lane * 4);
                acc.x = fmaf(w, v.x, acc.x);
                acc.y = fmaf(w, v.y, acc.y);
                acc.z = fmaf(w, v.z, acc.z);
                acc.w = fmaf(w, v.w, acc.w);
            }
            float4 r;
            r.x = fmaxf(fmaf(acc.x * rv, sc.x, bs.x), 0.0f);
            r.y = fmaxf(fmaf(acc.y * rv, sc.y, bs.y), 0.0f);
            r.z = fmaxf(fmaf(acc.z * rv, sc.z, bs.z), 0.0f);
            r.w = fmaxf(fmaf(acc.w * rv, sc.w, bs.w), 0.0f);
            *(float4*)(sh + d * PITCH + lane * 4) = r;
        }
    }
    __syncthreads();

    // -------- mean pool --------
    {
        int g = tid >> 7, f = tid & 127;
        float acc = 0.0f;
#pragma unroll 4
        for (int n = g * 32; n < g * 32 + 32; ++n) acc += sh[n * PITCH + f];
        pool[g * 128 + f] = acc;
    }
    __syncthreads();
    if (tid < 128)
        hp[tid] = (pool[tid] + pool[128 + tid] + pool[256 + tid] + pool[384 + tid])
                  * (1.0f / 128.0f);
    __syncthreads();

    // -------- MLP --------
    if (tid < 64) {
        float acc = b1[tid];
#pragma unroll 8
        for (int f = 0; f < 128; ++f) acc = fmaf(hp[f], w1[f * 64 + tid], acc);
        zz[tid] = fmaxf(acc, 0.0f);
    }
    __syncthreads();
    if (tid == 0) {
        float acc = b2[0];
#pragma unroll
        for (int j = 0; j < 64; ++j) acc = fmaf(zz[j], w2[j], acc);
        out[b] = acc;
    }
}

// ---------------------------------------------------------------------------
extern "C" void kernel_launch(void* const* d_in, const int* in_sizes, int n_in,
                              void* d_out, int out_size) {
    (void)in_sizes; (void)n_in; (void)out_size;
    const float* x    = (const float*)d_in[0];
    const int*   ei   = (const int*)d_in[1];
    const float* w_in = (const float*)d_in[2];
    const float* b_in = (const float*)d_in[3];
    const float* g0w  = (const float*)d_in[4];
    const float* g0as = (const float*)d_in[5];
    const float* g0ad = (const float*)d_in[6];
    const float* g0b  = (const float*)d_in[7];
    const float* bn0g = (const float*)d_in[8];
    const float* bn0b = (const float*)d_in[9];
    const float* bn0m = (const float*)d_in[10];
    const float* bn0v = (const float*)d_in[11];
    const float* g1w  = (const float*)d_in[12];
    const float* g1as = (const float*)d_in[13];
    const float* g1ad = (const float*)d_in[14];
    const float* g1b  = (const float*)d_in[15];
    const float* bn1g = (const float*)d_in[16];
    const float* bn1b = (const float*)d_in[17];
    const float* bn1m = (const float*)d_in[18];
    const float* bn1v = (const float*)d_in[19];
    const float* w1   = (const float*)d_in[20];
    const float* b1   = (const float*)d_in[21];
    const float* w2   = (const float*)d_in[22];
    const float* b2   = (const float*)d_in[23];
    float* out = (float*)d_out;

    cudaFuncSetAttribute(gnn_kernel,
                         cudaFuncAttributeMaxDynamicSharedMemorySize, SMEM_BYTES);

    build_csr_kernel<<<1, 1024>>>(ei);
    gnn_kernel<<<NGRAPH, NTHREADS, SMEM_BYTES>>>(
        x, w_in, b_in,
        g0w, g0as, g0ad, g0b, bn0g, bn0b, bn0m, bn0v,
        g1w, g1as, g1ad, g1b, bn1g, bn1b, bn1m, bn1v,
        w1, b1, w2, b2, out);
}

// round 4
// speedup vs baseline: 1.2319x; 1.2319x over previous
#include <cuda_runtime.h>

#define NNODE  128
#define NEDGE  1024
#define ETOT   1152
#define HFEAT  128
#define NGRAPH 1024
#define NTHREADS 512

// ---------------------------------------------------------------------------
// Device-global CSR (edge template shared by all graphs).
// ---------------------------------------------------------------------------
__device__ int g_csr_ptr[NNODE + 1];
__device__ int g_csr_src[ETOT];

__global__ void build_csr_kernel(const int* __restrict__ ei) {
    __shared__ int s_src[NEDGE];
    __shared__ int s_dst[NEDGE];
    __shared__ int cnt[NNODE];
    __shared__ int base[NNODE + 1];
    int t = threadIdx.x;
    if (t < NEDGE) { s_src[t] = ei[t]; s_dst[t] = ei[NEDGE + t]; }
    if (t < NNODE) cnt[t] = 0;
    __syncthreads();
    if (t < NEDGE) atomicAdd(&cnt[s_dst[t]], 1);
    __syncthreads();
    if (t == 0) {
        int acc = 0;
        for (int d = 0; d < NNODE; ++d) { base[d] = acc; acc += cnt[d] + 1; }
        base[NNODE] = acc;
    }
    __syncthreads();
    if (t <= NNODE) g_csr_ptr[t] = base[t];
    if (t < NEDGE) {
        int d = s_dst[t];
        int rank = 0;
        for (int e = 0; e < t; ++e) rank += (s_dst[e] == d) ? 1 : 0;
        g_csr_src[base[d] + rank] = s_src[t];
    }
    if (t < NNODE) g_csr_src[base[t] + cnt[t]] = t;  // self loop last
}

// ---------------------------------------------------------------------------
// Shared memory layout (floats; PITCH = 128, all hot accesses row-contiguous)
// ---------------------------------------------------------------------------
constexpr int OFF_SH    = 0;
constexpr int OFF_SXH   = OFF_SH  + NNODE * HFEAT;       // 16384
constexpr int OFF_SW    = OFF_SXH + NNODE * HFEAT;       // 16384 (sex overlaid)
constexpr int OFF_SS    = OFF_SW  + HFEAT * HFEAT;       // 512
constexpr int OFF_SD    = OFF_SS  + 512;
constexpr int OFF_RINV  = OFF_SD  + 512;
constexpr int OFF_SATT  = OFF_RINV + 512;                // 256
constexpr int OFF_SCALE = OFF_SATT + 256;                // 128
constexpr int OFF_BIAS  = OFF_SCALE + 128;               // 128
constexpr int OFF_POOL  = OFF_BIAS + 128;                // 512
constexpr int OFF_HP    = OFF_POOL + 512;                // 128
constexpr int OFF_ZZ    = OFF_HP + 128;                  // 64
constexpr int SM_FLOATS = OFF_ZZ + 64;
constexpr int SM_INTS   = 132 + ETOT;
constexpr int SMEM_BYTES = SM_FLOATS * 4 + SM_INTS * 4;   // ~212.9 KB

// ---------------------------------------------------------------------------
// Packed fp32x2 helpers (FFMA2 is PTX-only)
// ---------------------------------------------------------------------------
__device__ __forceinline__ unsigned long long pack2(float a) {
    unsigned long long r;
    unsigned int ai = __float_as_uint(a);
    asm("mov.b64 %0, {%1, %1};" : "=l"(r) : "r"(ai));
    return r;
}
__device__ __forceinline__ void ffma2(unsigned long long& d,
                                      unsigned long long a,
                                      unsigned long long b) {
    asm("fma.rn.f32x2 %0, %1, %2, %0;" : "+l"(d) : "l"(a), "l"(b));
}

// ---------------------------------------------------------------------------
// C[128,128] = A[128,128] @ W[128,128], all in SMEM (pitch 128).
// 8 warps (tid < 256). Warp tile: 16 rows x 128 cols. Thread tile: 8 x 8
// (cols ca..ca+3 and ca+64..ca+67). 128 MACs per L1 wavefront:
//  - A loads: LDS.64, 2 distinct addresses/warp (broadcast)
//  - W loads: LDS.128, lanes 0-15 contiguous 16B chunks (conflict-free)
// Caller handles __syncthreads around it.
// ---------------------------------------------------------------------------
__device__ __forceinline__ void gemm8x8(const float* __restrict__ A,
                                        const float* __restrict__ sW,
                                        float* __restrict__ C, int tid) {
    const int w  = tid >> 5;
    const int l  = tid & 31;
    const int r0 = w * 16 + (l >> 4) * 8;
    const int ca = (l & 15) * 4;

    unsigned long long acc[8][4];
#pragma unroll
    for (int i = 0; i < 8; ++i)
#pragma unroll
        for (int j = 0; j < 4; ++j) acc[i][j] = 0ull;

#pragma unroll 2
    for (int k = 0; k < HFEAT; k += 2) {
        float2 a[8];
#pragma unroll
        for (int i = 0; i < 8; ++i)
            a[i] = *(const float2*)(A + (r0 + i) * HFEAT + k);
        ulonglong2 w00 = *(const ulonglong2*)(sW + k * HFEAT + ca);
        ulonglong2 w01 = *(const ulonglong2*)(sW + k * HFEAT + ca + 64);
        ulonglong2 w10 = *(const ulonglong2*)(sW + (k + 1) * HFEAT + ca);
        ulonglong2 w11 = *(const ulonglong2*)(sW + (k + 1) * HFEAT + ca + 64);
#pragma unroll
        for (int i = 0; i < 8; ++i) {
            unsigned long long ax = pack2(a[i].x);
            unsigned long long ay = pack2(a[i].y);
            ffma2(acc[i][0], ax, w00.x);
            ffma2(acc[i][1], ax, w00.y);
            ffma2(acc[i][2], ax, w01.x);
            ffma2(acc[i][3], ax, w01.y);
            ffma2(acc[i][0], ay, w10.x);
            ffma2(acc[i][1], ay, w10.y);
            ffma2(acc[i][2], ay, w11.x);
            ffma2(acc[i][3], ay, w11.y);
        }
    }
#pragma unroll
    for (int i = 0; i < 8; ++i) {
        ulonglong2 s0, s1;
        s0.x = acc[i][0]; s0.y = acc[i][1];
        s1.x = acc[i][2]; s1.y = acc[i][3];
        *(ulonglong2*)(C + (r0 + i) * HFEAT + ca)      = s0;
        *(ulonglong2*)(C + (r0 + i) * HFEAT + ca + 64) = s1;
    }
}

__global__ __launch_bounds__(NTHREADS, 1)
void gnn_kernel(const float* __restrict__ x,
                const float* __restrict__ w_in, const float* __restrict__ b_in,
                const float* __restrict__ g0w, const float* __restrict__ g0as,
                const float* __restrict__ g0ad, const float* __restrict__ g0b,
                const float* __restrict__ bn0g, const float* __restrict__ bn0b,
                const float* __restrict__ bn0m, const float* __restrict__ bn0v,
                const float* __restrict__ g1w, const float* __restrict__ g1as,
                const float* __restrict__ g1ad, const float* __restrict__ g1b,
                const float* __restrict__ bn1g, const float* __restrict__ bn1b,
                const float* __restrict__ bn1m, const float* __restrict__ bn1v,
                const float* __restrict__ w1, const float* __restrict__ b1,
                const float* __restrict__ w2, const float* __restrict__ b2,
                float* __restrict__ out) {
    extern __shared__ float smem[];
    float* sh    = smem + OFF_SH;
    float* sxh   = smem + OFF_SXH;
    float* sW    = smem + OFF_SW;
    float* sex   = smem + OFF_SW;     // overlaid: sex lifetime disjoint from W use
    float* s_s   = smem + OFF_SS;
    float* s_d   = smem + OFF_SD;
    float* rinv  = smem + OFF_RINV;
    float* satt  = smem + OFF_SATT;
    float* sscale= smem + OFF_SCALE;
    float* sbias = smem + OFF_BIAS;
    float* pool  = smem + OFF_POOL;
    float* hp    = smem + OFF_HP;
    float* zz    = smem + OFF_ZZ;
    int*   sptr  = (int*)(smem + SM_FLOATS);
    int*   scsr  = sptr + 132;

    const int tid  = threadIdx.x;
    const int wid  = tid >> 5;
    const int lane = tid & 31;
    const int b    = blockIdx.x;

    // stage CSR
    for (int i = tid; i <= NNODE; i += NTHREADS) sptr[i] = g_csr_ptr[i];
    for (int i = tid; i < ETOT; i += NTHREADS)   scsr[i] = g_csr_src[i];

    // stage W0 (resident), attention vecs, BN0 fold
    for (int i = tid; i < HFEAT * HFEAT / 4; i += NTHREADS)
        *(float4*)(sW + i * 4) = *(const float4*)(g0w + i * 4);
    if (tid < 128) {
        satt[tid]       = g0as[tid];
        satt[128 + tid] = g0ad[tid];
        float sc = bn0g[tid] * rsqrtf(bn0v[tid] + 1e-5f);
        sscale[tid] = sc;
        sbias[tid]  = fmaf(g0b[tid] - bn0m[tid], sc, bn0b[tid]);
    }

    // input projection: h = relu(x_n * w_in + b_in)
    const float* xr = x + b * NNODE;
    for (int it = tid; it < NNODE * 32; it += NTHREADS) {
        int n = it >> 5, fq = it & 31;
        float xv = xr[n];
        float4 w  = *(const float4*)(w_in + fq * 4);
        float4 bb = *(const float4*)(b_in + fq * 4);
        float4 r;
        r.x = fmaxf(fmaf(xv, w.x, bb.x), 0.0f);
        r.y = fmaxf(fmaf(xv, w.y, bb.y), 0.0f);
        r.z = fmaxf(fmaf(xv, w.z, bb.z), 0.0f);
        r.w = fmaxf(fmaf(xv, w.w, bb.w), 0.0f);
        *(float4*)(sh + n * HFEAT + fq * 4) = r;
    }
    __syncthreads();

    // ==================== GAT layer 0 ====================
    if (tid < 256) gemm8x8(sh, sW, sxh, tid);
    __syncthreads();

    // per-(node, head) scores
    {
        int n  = tid & 127;
        int hh = tid >> 7;
        const float* row = &sxh[n * HFEAT + hh * 32];
        const float* as  = &satt[hh * 32];
        const float* ad  = &satt[128 + hh * 32];
        float ssum = 0.0f, dsum = 0.0f;
#pragma unroll
        for (int q = 0; q < 8; ++q) {
            float4 v  = *(const float4*)(row + q * 4);
            float4 a1 = *(const float4*)(as + q * 4);
            float4 a2 = *(const float4*)(ad + q * 4);
            ssum = fmaf(v.x, a1.x, fmaf(v.y, a1.y, fmaf(v.z, a1.z, fmaf(v.w, a1.w, ssum))));
            dsum = fmaf(v.x, a2.x, fmaf(v.y, a2.y, fmaf(v.z, a2.z, fmaf(v.w, a2.w, dsum))));
        }
        s_s[n * 4 + hh] = ssum;
        s_d[n * 4 + hh] = dsum;
    }
    __syncthreads();   // also ends all reads of sW(g0w): sex may now be written

    // softmax per (dst, head)
    {
        int d  = tid & 127;
        int hh = tid >> 7;
        int beg = sptr[d], end = sptr[d + 1];
        float sd = s_d[d * 4 + hh];
        float mx = -1e30f;
        for (int p = beg; p < end; ++p) {
            float e = s_s[scsr[p] * 4 + hh] + sd;
            e = (e > 0.0f) ? e : 0.2f * e;
            mx = fmaxf(mx, e);
        }
        float sum = 0.0f;
        for (int p = beg; p < end; ++p) {
            float e = s_s[scsr[p] * 4 + hh] + sd;
            e = (e > 0.0f) ? e : 0.2f * e;
            float ex = __expf(e - mx);
            sex[p * 4 + hh] = ex;
            sum += ex;
        }
        rinv[d * 4 + hh] = 1.0f / sum;
    }
    __syncthreads();

    // aggregate + BN0 + relu (warp-per-node, float4 per lane) -> sh
    {
        int hh = lane >> 3;
        float4 sc = *(const float4*)(sscale + lane * 4);
        float4 bs = *(const float4*)(sbias + lane * 4);
        for (int d = wid; d < NNODE; d += 16) {
            int beg = sptr[d], end = sptr[d + 1];
            float rv = rinv[d * 4 + hh];
            float4 acc = make_float4(0.f, 0.f, 0.f, 0.f);
            for (int p = beg; p < end; ++p) {
                float w = sex[p * 4 + hh];
                const float4 v = *(const float4*)(sxh + scsr[p] * HFEAT + lane * 4);
                acc.x = fmaf(w, v.x, acc.x);
                acc.y = fmaf(w, v.y, acc.y);
                acc.z = fmaf(w, v.z, acc.z);
                acc.w = fmaf(w, v.w, acc.w);
            }
            float4 r;
            r.x = fmaxf(fmaf(acc.x * rv, sc.x, bs.x), 0.0f);
            r.y = fmaxf(fmaf(acc.y * rv, sc.y, bs.y), 0.0f);
            r.z = fmaxf(fmaf(acc.z * rv, sc.z, bs.z), 0.0f);
            r.w = fmaxf(fmaf(acc.w * rv, sc.w, bs.w), 0.0f);
            *(float4*)(sh + d * HFEAT + lane * 4) = r;
        }
    }
    __syncthreads();   // sex reads done -> sW region reusable

    // stage W1 over sex/sW + layer-1 attention + BN1 fold
    for (int i = tid; i < HFEAT * HFEAT / 4; i += NTHREADS)
        *(float4*)(sW + i * 4) = *(const float4*)(g1w + i * 4);
    if (tid < 128) {
        float sc = bn1g[tid] * rsqrtf(bn1v[tid] + 1e-5f);
        sscale[tid] = sc;
        sbias[tid]  = fmaf(g1b[tid] - bn1m[tid], sc, bn1b[tid]);
        satt[tid]       = g1as[tid];
        satt[128 + tid] = g1ad[tid];
    }
    __syncthreads();

    // ==================== GAT layer 1 ====================
    if (tid < 256) gemm8x8(sh, sW, sxh, tid);
    __syncthreads();

    // scores: warp per node, shuffle reduce
    {
        float4 a1 = *(const float4*)(satt + lane * 4);
        float4 a2 = *(const float4*)(satt + 128 + lane * 4);
        for (int nd = wid; nd < NNODE; nd += 16) {
            float4 v = *(const float4*)(sxh + nd * HFEAT + lane * 4);
            float ss = v.x*a1.x + v.y*a1.y + v.z*a1.z + v.w*a1.w;
            float dd = v.x*a2.x + v.y*a2.y + v.z*a2.z + v.w*a2.w;
#pragma unroll
            for (int o = 16; o; o >>= 1) {
                ss += __shfl_xor_sync(0xffffffffu, ss, o);
                dd += __shfl_xor_sync(0xffffffffu, dd, o);
            }
            if (lane == 0) { s_s[nd] = ss; s_d[nd] = dd; }
        }
    }
    __syncthreads();   // scores ready; sW(g1w) reads done -> sex writable

    if (tid < 128) {
        int d = tid;
        int beg = sptr[d], end = sptr[d + 1];
        float sd = s_d[d];
        float mx = -1e30f;
        for (int p = beg; p < end; ++p) {
            float e = s_s[scsr[p]] + sd;
            e = (e > 0.0f) ? e : 0.2f * e;
            mx = fmaxf(mx, e);
        }
        float sum = 0.0f;
        for (int p = beg; p < end; ++p) {
            float e = s_s[scsr[p]] + sd;
            e = (e > 0.0f) ? e : 0.2f * e;
            float ex = __expf(e - mx);
            sex[p] = ex;
            sum += ex;
        }
        rinv[d] = 1.0f / sum;
    }
    __syncthreads();

    // aggregate + BN1 + relu -> sh
    {
        float4 sc = *(const float4*)(sscale + lane * 4);
        float4 bs = *(const float4*)(sbias + lane * 4);
        for (int d = wid; d < NNODE; d += 16) {
            int beg = sptr[d], end = sptr[d + 1];
            float rv = rinv[d];
            float4 acc = make_float4(0.f, 0.f, 0.f, 0.f);
            for (int p = beg; p < end; ++p) {
                float w = sex[p];
                const float4 v = *(const float4*)(sxh + scsr[p] * HFEAT + lane * 4);
                acc.x = fmaf(w, v.x, acc.x);
                acc.y = fmaf(w, v.y, acc.y);
                acc.z = fmaf(w, v.z, acc.z);
                acc.w = fmaf(w, v.w, acc.w);
            }
            float4 r;
            r.x = fmaxf(fmaf(acc.x * rv, sc.x, bs.x), 0.0f);
            r.y = fmaxf(fmaf(acc.y * rv, sc.y, bs.y), 0.0f);
            r.z = fmaxf(fmaf(acc.z * rv, sc.z, bs.z), 0.0f);
            r.w = fmaxf(fmaf(acc.w * rv, sc.w, bs.w), 0.0f);
            *(float4*)(sh + d * HFEAT + lane * 4) = r;
        }
    }
    __syncthreads();

    // -------- mean pool --------
    {
        int g = tid >> 7, f = tid & 127;
        float acc = 0.0f;
#pragma unroll 4
        for (int n = g * 32; n < g * 32 + 32; ++n) acc += sh[n * HFEAT + f];
        pool[g * 128 + f] = acc;
    }
    __syncthreads();
    if (tid < 128)
        hp[tid] = (pool[tid] + pool[128 + tid] + pool[256 + tid] + pool[384 + tid])
                  * (1.0f / 128.0f);
    __syncthreads();

    // -------- MLP --------
    if (tid < 64) {
        float acc = b1[tid];
#pragma unroll 8
        for (int f = 0; f < 128; ++f) acc = fmaf(hp[f], w1[f * 64 + tid], acc);
        zz[tid] = fmaxf(acc, 0.0f);
    }
    __syncthreads();
    if (tid == 0) {
        float acc = b2[0];
#pragma unroll
        for (int j = 0; j < 64; ++j) acc = fmaf(zz[j], w2[j], acc);
        out[b] = acc;
    }
}

// ---------------------------------------------------------------------------
extern "C" void kernel_launch(void* const* d_in, const int* in_sizes, int n_in,
                              void* d_out, int out_size) {
    (void)in_sizes; (void)n_in; (void)out_size;
    const float* x    = (const float*)d_in[0];
    const int*   ei   = (const int*)d_in[1];
    const float* w_in = (const float*)d_in[2];
    const float* b_in = (const float*)d_in[3];
    const float* g0w  = (const float*)d_in[4];
    const float* g0as = (const float*)d_in[5];
    const float* g0ad = (const float*)d_in[6];
    const float* g0b  = (const float*)d_in[7];
    const float* bn0g = (const float*)d_in[8];
    const float* bn0b = (const float*)d_in[9];
    const float* bn0m = (const float*)d_in[10];
    const float* bn0v = (const float*)d_in[11];
    const float* g1w  = (const float*)d_in[12];
    const float* g1as = (const float*)d_in[13];
    const float* g1ad = (const float*)d_in[14];
    const float* g1b  = (const float*)d_in[15];
    const float* bn1g = (const float*)d_in[16];
    const float* bn1b = (const float*)d_in[17];
    const float* bn1m = (const float*)d_in[18];
    const float* bn1v = (const float*)d_in[19];
    const float* w1   = (const float*)d_in[20];
    const float* b1   = (const float*)d_in[21];
    const float* w2   = (const float*)d_in[22];
    const float* b2   = (const float*)d_in[23];
    float* out = (float*)d_out;

    cudaFuncSetAttribute(gnn_kernel,
                         cudaFuncAttributeMaxDynamicSharedMemorySize, SMEM_BYTES);

    build_csr_kernel<<<1, 1024>>>(ei);
    gnn_kernel<<<NGRAPH, NTHREADS, SMEM_BYTES>>>(
        x, w_in, b_in,
        g0w, g0as, g0ad, g0b, bn0g, bn0b, bn0m, bn0v,
        g1w, g1as, g1ad, g1b, bn1g, bn1b, bn1m, bn1v,
        w1, b1, w2, b2, out);
}